// round 14
// baseline (speedup 1.0000x reference)
#include <cuda_runtime.h>
#include <cuda_fp16.h>
#include <math.h>
#include <cstdint>

#define NN 50000
#define EDG 400000
#define DIM 64
#define NH 4
#define HD 256
#define NL 3
#define NC 10
#define NG 512
#define SCAN_B 1024
#define NSB ((NN + SCAN_B - 1) / SCAN_B)

typedef unsigned long long u64;
typedef unsigned int u32;

// ---------------- scratch ----------------------------------------------------
__device__ __align__(16) float g_x[NN * DIM];
__device__ __align__(16) __half g_xl16[NN * HD];   // fp16: attention-only consumers
__device__ __align__(16) __half g_xr16[NN * HD];
__device__ int   g_deg[NN];
__device__ int   g_rowptr[NN + 1];
__device__ int   g_cursor[NN];
__device__ int   g_csrc[EDG];
__device__ int   g_bsum[64];
__device__ int   g_boff[64];
__device__ float g_pool[NG * DIM];
__device__ float g_cnt[NG];
// W fp16 image: [L][n=512][k=64], n over [Wl | Wr] columns
__device__ __align__(16) __half g_wh[NL * 512 * 64];

// ---------------- atom encoder (+ scratch zero + wprep fused) -----------------
__global__ void k_encoder(const int* __restrict__ feat, const float* __restrict__ emb,
                          const float* __restrict__ Wl, const float* __restrict__ Wr) {
    int t = blockIdx.x * blockDim.x + threadIdx.x;
    if (t < NN) g_deg[t] = 0;
    if (t < NG * DIM) g_pool[t] = 0.f;
    if (t < NG) g_cnt[t] = 0.f;
    // fused wprep: W -> fp16 image [l][n][k]
    if (t < NL * 512 * 32) {
        int kp = t & 31;
        int n = (t >> 5) & 511;
        int l = t >> 14;
        int k0 = kp * 2;
        const float* W = (n < 256) ? Wl : Wr;
        int nn = n & 255;
        float w0 = W[(l * 64 + k0) * 256 + nn];
        float w1 = W[(l * 64 + k0 + 1) * 256 + nn];
        *(__half2*)(g_wh + (size_t)l * 32768 + n * 64 + k0) = __floats2half2_rn(w0, w1);
    }
    if (t >= NN * DIM) return;
    int n = t >> 6, d = t & 63;
    const int offs[9] = {0, 119, 124, 136, 148, 158, 164, 170, 172};
    float s = 0.f;
#pragma unroll
    for (int j = 0; j < 9; j++) {
        int idx = feat[n * 9 + j] + offs[j];
        s += emb[idx * DIM + d];
    }
    g_x[t] = s;
}

// ---------------- CSR build --------------------------------------------------
__global__ void k_hist(const int* __restrict__ dst) {
    int e = blockIdx.x * blockDim.x + threadIdx.x;
    if (e < EDG) atomicAdd(&g_deg[dst[e]], 1);
}
__global__ __launch_bounds__(SCAN_B) void k_scanA() {
    __shared__ int sh[SCAN_B];
    int b = blockIdx.x, t = threadIdx.x;
    int i = b * SCAN_B + t;
    int v = (i < NN) ? g_deg[i] : 0;
    sh[t] = v;
    __syncthreads();
    for (int o = 1; o < SCAN_B; o <<= 1) {
        int u = (t >= o) ? sh[t - o] : 0;
        __syncthreads();
        sh[t] += u;
        __syncthreads();
    }
    if (i < NN) g_rowptr[i] = sh[t] - v;
    if (t == SCAN_B - 1) g_bsum[b] = sh[t];
}
__global__ void k_scanB() {
    __shared__ int sh[64];
    int t = threadIdx.x;
    int v = (t < NSB) ? g_bsum[t] : 0;
    sh[t] = v;
    __syncthreads();
    for (int o = 1; o < 64; o <<= 1) {
        int u = (t >= o) ? sh[t - o] : 0;
        __syncthreads();
        sh[t] += u;
        __syncthreads();
    }
    g_boff[t] = sh[t] - v;
    if (t == NSB - 1) g_rowptr[NN] = sh[t];
}
__global__ void k_scanC() {
    int i = blockIdx.x * blockDim.x + threadIdx.x;
    if (i < NN) {
        int r = g_rowptr[i] + g_boff[i / SCAN_B];
        g_rowptr[i] = r;
        g_cursor[i] = r;
    }
}
__global__ void k_scatter(const int* __restrict__ src, const int* __restrict__ dst) {
    int e = blockIdx.x * blockDim.x + threadIdx.x;
    if (e < EDG) {
        int d = dst[e];
        int pos = atomicAdd(&g_cursor[d], 1);
        g_csrc[pos] = src[e];
    }
}

// ---------------- HMMA GEMM: [xl|xr] = x @ [Wl|Wr] + bias (fp16 in/out) -------
// CTA: 128 rows, loops over 4 column-chunks of 128. Dynamic smem 36,864B.
// 8 warps (4m x 2n), warp tile 32x64. Single-pass fp16 MMA, fp32 accumulate.
// Weight image indexed from DEVICE code via layer index (host shadow-symbol trap).
#define ASTR 72
#define GSMEM ((128 * ASTR + 128 * ASTR) * 2)   // 36864 bytes

__device__ __forceinline__ void mma16816(float c[4], u32 a0, u32 a1, u32 a2, u32 a3,
                                         u32 b0, u32 b1) {
    asm volatile("mma.sync.aligned.m16n8k16.row.col.f32.f16.f16.f32 "
                 "{%0,%1,%2,%3}, {%4,%5,%6,%7}, {%8,%9}, {%0,%1,%2,%3};"
                 : "+f"(c[0]), "+f"(c[1]), "+f"(c[2]), "+f"(c[3])
                 : "r"(a0), "r"(a1), "r"(a2), "r"(a3), "r"(b0), "r"(b1));
}

__global__ __launch_bounds__(256) void k_gemm_mma(int layer,
                                                  const float* __restrict__ bl,
                                                  const float* __restrict__ br) {
    extern __shared__ __half smem[];
    __half* sA = smem;                 // 128*ASTR
    __half* sB = sA + 128 * ASTR;      // 128*ASTR

    const __half* Wh = g_wh + (size_t)layer * 32768;

    int tid = threadIdx.x;
    int bm = blockIdx.x * 128;

    // A: 128x64 fp32 -> fp16 (once per CTA)
    for (int i = tid; i < 128 * 32; i += 256) {
        int m = i >> 5, kp = i & 31;
        int row = bm + m;
        float2 v = make_float2(0.f, 0.f);
        if (row < NN) v = *(const float2*)(g_x + (size_t)row * DIM + kp * 2);
        *(__half2*)&sA[m * ASTR + kp * 2] = __floats2half2_rn(v.x, v.y);
    }

    int wid = tid >> 5, lane = tid & 31;
    int wm = wid >> 1, wn = wid & 1;     // 4x2 warps, warp tile 32 rows x 64 cols
    int gq = lane >> 2, tq = lane & 3;

    for (int nc = 0; nc < 4; nc++) {
        int bc = nc * 128;
        __syncthreads();   // iter0: publish A; later: protect B reuse
        // B chunk: 128 cols x 64 k
        for (int i = tid; i < 128 * 32; i += 256) {
            int n = i >> 5, kp = i & 31;
            size_t go = (size_t)(bc + n) * 64 + kp * 2;
            *(u32*)&sB[n * ASTR + kp * 2] = *(const u32*)(Wh + go);
        }
        __syncthreads();

        float C[2][8][4];
#pragma unroll
        for (int i = 0; i < 2; i++)
#pragma unroll
            for (int j = 0; j < 8; j++)
#pragma unroll
                for (int q = 0; q < 4; q++) C[i][j][q] = 0.f;

#pragma unroll
        for (int kk = 0; kk < 4; kk++) {
            int k0 = kk * 16 + tq * 2;
            u32 a[2][4];
#pragma unroll
            for (int i = 0; i < 2; i++) {
                int r = wm * 32 + i * 16 + gq;
                a[i][0] = *(const u32*)&sA[r * ASTR + k0];
                a[i][1] = *(const u32*)&sA[(r + 8) * ASTR + k0];
                a[i][2] = *(const u32*)&sA[r * ASTR + k0 + 8];
                a[i][3] = *(const u32*)&sA[(r + 8) * ASTR + k0 + 8];
            }
            u32 b[8][2];
#pragma unroll
            for (int j = 0; j < 8; j++) {
                int c = wn * 64 + j * 8 + gq;
                b[j][0] = *(const u32*)&sB[c * ASTR + k0];
                b[j][1] = *(const u32*)&sB[c * ASTR + k0 + 8];
            }
#pragma unroll
            for (int i = 0; i < 2; i++)
#pragma unroll
                for (int j = 0; j < 8; j++)
                    mma16816(C[i][j], a[i][0], a[i][1], a[i][2], a[i][3], b[j][0], b[j][1]);
        }

        // epilogue: bias + fp16 store this 128-col chunk
#pragma unroll
        for (int j = 0; j < 8; j++) {
            int col = bc + wn * 64 + j * 8 + tq * 2;   // 0..511
            __half* base; const float* bias;
            if (col < 256) { base = g_xl16; bias = bl; }
            else           { base = g_xr16; bias = br; col -= 256; }
            float b0 = bias[col], b1 = bias[col + 1];
#pragma unroll
            for (int i = 0; i < 2; i++) {
                int r0 = bm + wm * 32 + i * 16 + gq;
                if (r0 < NN)
                    *(__half2*)(base + (size_t)r0 * HD + col) =
                        __floats2half2_rn(C[i][j][0] + b0, C[i][j][1] + b1);
                int r1 = r0 + 8;
                if (r1 < NN)
                    *(__half2*)(base + (size_t)r1 * HD + col) =
                        __floats2half2_rn(C[i][j][2] + b0, C[i][j][3] + b1);
            }
        }
    }
}

// ---------------- fused attention --------------------------------------------
__device__ __forceinline__ float lrelu(float v) { return v > 0.f ? v : 0.2f * v; }

// unpack 8 halfs (uint4) -> two float4
__device__ __forceinline__ void h8f(uint4 v, float4& a, float4& b) {
    __half2* h = (__half2*)&v;
    float2 f0 = __half22float2(h[0]);
    float2 f1 = __half22float2(h[1]);
    float2 f2 = __half22float2(h[2]);
    float2 f3 = __half22float2(h[3]);
    a = make_float4(f0.x, f0.y, f1.x, f1.y);
    b = make_float4(f2.x, f2.y, f3.x, f3.y);
}

__device__ __forceinline__ float edge_score(float4 ta, float4 tb,
                                            float4 xra, float4 xrb,
                                            float4 ata, float4 atb) {
    float p = lrelu(ta.x + xra.x) * ata.x + lrelu(ta.y + xra.y) * ata.y
            + lrelu(ta.z + xra.z) * ata.z + lrelu(ta.w + xra.w) * ata.w
            + lrelu(tb.x + xrb.x) * atb.x + lrelu(tb.y + xrb.y) * atb.y
            + lrelu(tb.z + xrb.z) * atb.z + lrelu(tb.w + xrb.w) * atb.w;
    p += __shfl_xor_sync(0xffffffffu, p, 1);
    p += __shfl_xor_sync(0xffffffffu, p, 2);
    p += __shfl_xor_sync(0xffffffffu, p, 4);
    return p;
}

// one warp per destination node; lane owns halfs [8*lane, 8*lane+8) (one uint4)
// dopool: last layer adds result straight into g_pool/g_cnt (no g_x store)
__global__ __launch_bounds__(256) void k_attn(const float* __restrict__ att,
                                              const float* __restrict__ gb, int dogelu,
                                              const int* __restrict__ batch, int dopool) {
    int w = (blockIdx.x * blockDim.x + threadIdx.x) >> 5;
    int lane = threadIdx.x & 31;
    if (w >= NN) return;

    float4 xra, xrb;
    h8f(*(const uint4*)(g_xr16 + (size_t)w * HD + lane * 8), xra, xrb);
    const float4* at4 = (const float4*)att;
    float4 ata = at4[2 * lane], atb = at4[2 * lane + 1];

    float4 sa, sb;
    h8f(*(const uint4*)(g_xl16 + (size_t)w * HD + lane * 8), sa, sb);

    int beg = g_rowptr[w], end = g_rowptr[w + 1];
    int j = beg;
    bool have = (j < end);
    int snext = (j + 1 < end) ? g_csrc[j + 1] : 0;
    uint4 nv;
    if (have) {
        int s = g_csrc[j];
        nv = *(const uint4*)(g_xl16 + (size_t)s * HD + lane * 8);
    }

    float denom;
    float acc[8];
    {   // self-loop edge
        float e = edge_score(sa, sb, xra, xrb, ata, atb);
        float ea = __expf(e);
        denom = ea;
        acc[0] = ea * sa.x; acc[1] = ea * sa.y; acc[2] = ea * sa.z; acc[3] = ea * sa.w;
        acc[4] = ea * sb.x; acc[5] = ea * sb.y; acc[6] = ea * sb.z; acc[7] = ea * sb.w;
    }
    while (have) {
        float4 ta, tb;
        h8f(nv, ta, tb);
        j++;
        have = (j < end);
        int s = snext;
        snext = (j + 1 < end) ? g_csrc[j + 1] : 0;
        if (have) nv = *(const uint4*)(g_xl16 + (size_t)s * HD + lane * 8);

        float e = edge_score(ta, tb, xra, xrb, ata, atb);
        float ea = __expf(e);
        denom += ea;
        acc[0] += ea * ta.x; acc[1] += ea * ta.y; acc[2] += ea * ta.z; acc[3] += ea * ta.w;
        acc[4] += ea * tb.x; acc[5] += ea * tb.y; acc[6] += ea * tb.z; acc[7] += ea * tb.w;
    }

    float inv = 1.f / denom;
    float r[8];
#pragma unroll
    for (int c = 0; c < 8; c++) {
        float v = acc[c] * inv;
        v += __shfl_xor_sync(0xffffffffu, v, 8);
        v += __shfl_xor_sync(0xffffffffu, v, 16);
        v *= 0.25f;
        r[c] = v;
    }
    int d0 = 8 * (lane & 7);
#pragma unroll
    for (int c = 0; c < 8; c++) {
        float s = r[c] + gb[d0 + c];
        if (dogelu) s = 0.5f * s * (1.f + erff(s * 0.70710678118654752f));
        r[c] = s;
    }
    if (dopool) {
        int gix = batch[w];
        if (lane < 8) {
            float* p = g_pool + (size_t)gix * DIM + d0;
#pragma unroll
            for (int c = 0; c < 8; c++) atomicAdd(&p[c], r[c]);
        }
        if (lane == 0) atomicAdd(&g_cnt[gix], 1.f);
    } else if (lane < 8) {
        *(float4*)(g_x + (size_t)w * DIM + d0)     = make_float4(r[0], r[1], r[2], r[3]);
        *(float4*)(g_x + (size_t)w * DIM + d0 + 4) = make_float4(r[4], r[5], r[6], r[7]);
    }
}

// ---------------- head -------------------------------------------------------
__global__ void k_final(const float* __restrict__ Wc, const float* __restrict__ bc,
                        float* __restrict__ out) {
    int g = blockIdx.x;
    int lane = threadIdx.x;
    float inv = 1.f / fmaxf(g_cnt[g], 1.f);
    float p0 = g_pool[g * DIM + lane] * inv;
    float p1 = g_pool[g * DIM + 32 + lane] * inv;
#pragma unroll
    for (int c = 0; c < NC; c++) {
        float s = p0 * Wc[lane * NC + c] + p1 * Wc[(lane + 32) * NC + c];
#pragma unroll
        for (int o = 16; o; o >>= 1) s += __shfl_xor_sync(0xffffffffu, s, o);
        if (lane == 0) out[g * NC + c] = s + bc[c];
    }
}

// ---------------- launch ------------------------------------------------------
extern "C" void kernel_launch(void* const* d_in, const int* in_sizes, int n_in,
                              void* d_out, int out_size) {
    (void)in_sizes; (void)n_in; (void)out_size;
    const int*   feat  = (const int*)  d_in[0];
    const int*   econ  = (const int*)  d_in[1];
    const int*   batch = (const int*)  d_in[2];
    const float* emb   = (const float*)d_in[3];
    const float* Wl    = (const float*)d_in[4];
    const float* bl    = (const float*)d_in[5];
    const float* Wr    = (const float*)d_in[6];
    const float* br    = (const float*)d_in[7];
    const float* att   = (const float*)d_in[8];
    const float* gbias = (const float*)d_in[9];
    const float* Wc    = (const float*)d_in[10];
    const float* bcv   = (const float*)d_in[11];
    float* out = (float*)d_out;

    const int* src = econ;
    const int* dst = econ + EDG;

    cudaFuncSetAttribute(k_gemm_mma, cudaFuncAttributeMaxDynamicSharedMemorySize, GSMEM);

    k_encoder<<<(NN * DIM + 255) / 256, 256>>>(feat, emb, Wl, Wr);

    k_hist<<<(EDG + 255) / 256, 256>>>(dst);
    k_scanA<<<NSB, SCAN_B>>>();
    k_scanB<<<1, 64>>>();
    k_scanC<<<(NN + 255) / 256, 256>>>();
    k_scatter<<<(EDG + 255) / 256, 256>>>(src, dst);

    for (int l = 0; l < NL; l++) {
        k_gemm_mma<<<(NN + 127) / 128, 256, GSMEM>>>(l, bl + l * HD, br + l * HD);
        k_attn<<<(NN * 32 + 255) / 256, 256>>>(att + l * NH * DIM, gbias + l * DIM,
                                               (l < NL - 1) ? 1 : 0,
                                               batch, (l == NL - 1) ? 1 : 0);
    }

    k_final<<<NG, 32>>>(Wc, bcv, out);
}

// round 15
// speedup vs baseline: 1.1430x; 1.1430x over previous
#include <cuda_runtime.h>
#include <cuda_fp16.h>
#include <math.h>
#include <cstdint>

#define NN 50000
#define EDG 400000
#define DIM 64
#define NH 4
#define HD 256
#define NL 3
#define NC 10
#define NG 512
#define SCAN_B 1024
#define NSB ((NN + SCAN_B - 1) / SCAN_B)

typedef unsigned long long u64;
typedef unsigned int u32;

// ---------------- scratch ----------------------------------------------------
__device__ __align__(16) float g_x[NN * DIM];
__device__ __align__(16) __half g_xl16[NN * HD];   // fp16: attention-only consumers
__device__ __align__(16) __half g_xr16[NN * HD];
__device__ int   g_deg[NN];
__device__ int   g_rowptr[NN + 1];
__device__ int   g_cursor[NN];
__device__ int   g_csrc[EDG];
__device__ int   g_bsum[64];
__device__ int   g_boff[64];
__device__ float g_pool[NG * DIM];
__device__ float g_cnt[NG];
// W fp16 image: [L][n=512][k=64], n over [Wl | Wr] columns
__device__ __align__(16) __half g_wh[NL * 512 * 64];

// ---------------- atom encoder (+ scratch zero + wprep fused) -----------------
__global__ void k_encoder(const int* __restrict__ feat, const float* __restrict__ emb,
                          const float* __restrict__ Wl, const float* __restrict__ Wr) {
    int t = blockIdx.x * blockDim.x + threadIdx.x;
    if (t < NN) g_deg[t] = 0;
    if (t < NG * DIM) g_pool[t] = 0.f;
    if (t < NG) g_cnt[t] = 0.f;
    // fused wprep: W -> fp16 image [l][n][k]
    if (t < NL * 512 * 32) {
        int kp = t & 31;
        int n = (t >> 5) & 511;
        int l = t >> 14;
        int k0 = kp * 2;
        const float* W = (n < 256) ? Wl : Wr;
        int nn = n & 255;
        float w0 = W[(l * 64 + k0) * 256 + nn];
        float w1 = W[(l * 64 + k0 + 1) * 256 + nn];
        *(__half2*)(g_wh + (size_t)l * 32768 + n * 64 + k0) = __floats2half2_rn(w0, w1);
    }
    if (t >= NN * DIM) return;
    int n = t >> 6, d = t & 63;
    const int offs[9] = {0, 119, 124, 136, 148, 158, 164, 170, 172};
    float s = 0.f;
#pragma unroll
    for (int j = 0; j < 9; j++) {
        int idx = feat[n * 9 + j] + offs[j];
        s += emb[idx * DIM + d];
    }
    g_x[t] = s;
}

// ---------------- CSR build --------------------------------------------------
__global__ void k_hist(const int* __restrict__ dst) {
    int e = blockIdx.x * blockDim.x + threadIdx.x;
    if (e < EDG) atomicAdd(&g_deg[dst[e]], 1);
}
__global__ __launch_bounds__(SCAN_B) void k_scanA() {
    __shared__ int sh[SCAN_B];
    int b = blockIdx.x, t = threadIdx.x;
    int i = b * SCAN_B + t;
    int v = (i < NN) ? g_deg[i] : 0;
    sh[t] = v;
    __syncthreads();
    for (int o = 1; o < SCAN_B; o <<= 1) {
        int u = (t >= o) ? sh[t - o] : 0;
        __syncthreads();
        sh[t] += u;
        __syncthreads();
    }
    if (i < NN) g_rowptr[i] = sh[t] - v;
    if (t == SCAN_B - 1) g_bsum[b] = sh[t];
}
__global__ void k_scanB() {
    __shared__ int sh[64];
    int t = threadIdx.x;
    int v = (t < NSB) ? g_bsum[t] : 0;
    sh[t] = v;
    __syncthreads();
    for (int o = 1; o < 64; o <<= 1) {
        int u = (t >= o) ? sh[t - o] : 0;
        __syncthreads();
        sh[t] += u;
        __syncthreads();
    }
    g_boff[t] = sh[t] - v;
    if (t == NSB - 1) g_rowptr[NN] = sh[t];
}
__global__ void k_scanC() {
    int i = blockIdx.x * blockDim.x + threadIdx.x;
    if (i < NN) {
        int r = g_rowptr[i] + g_boff[i / SCAN_B];
        g_rowptr[i] = r;
        g_cursor[i] = r;
    }
}
__global__ void k_scatter(const int* __restrict__ src, const int* __restrict__ dst) {
    int e = blockIdx.x * blockDim.x + threadIdx.x;
    if (e < EDG) {
        int d = dst[e];
        int pos = atomicAdd(&g_cursor[d], 1);
        g_csrc[pos] = src[e];
    }
}

// ---------------- HMMA GEMM: [xl|xr] = x @ [Wl|Wr] + bias (fp16 in/out) -------
// CTA: 128 rows, loops over 8 column-chunks of 64. Dynamic smem 27,648B.
// 8 warps (4m x 2n), warp tile 32x32. Single-pass fp16 MMA, fp32 accumulate.
// DO NOT widen the N warp tile (32x64 regressed twice: R10, R14 — reg pressure).
#define ASTR 72
#define GSMEM ((128 * ASTR + 64 * ASTR) * 2)   // 27648 bytes

__device__ __forceinline__ void mma16816(float c[4], u32 a0, u32 a1, u32 a2, u32 a3,
                                         u32 b0, u32 b1) {
    asm volatile("mma.sync.aligned.m16n8k16.row.col.f32.f16.f16.f32 "
                 "{%0,%1,%2,%3}, {%4,%5,%6,%7}, {%8,%9}, {%0,%1,%2,%3};"
                 : "+f"(c[0]), "+f"(c[1]), "+f"(c[2]), "+f"(c[3])
                 : "r"(a0), "r"(a1), "r"(a2), "r"(a3), "r"(b0), "r"(b1));
}

__global__ __launch_bounds__(256) void k_gemm_mma(int layer,
                                                  const float* __restrict__ bl,
                                                  const float* __restrict__ br) {
    extern __shared__ __half smem[];
    __half* sA = smem;                 // 128*ASTR
    __half* sB = sA + 128 * ASTR;      // 64*ASTR

    const __half* Wh = g_wh + (size_t)layer * 32768;

    int tid = threadIdx.x;
    int bm = blockIdx.x * 128;

    // A: 128x64 fp32 -> fp16 (once per CTA)
    for (int i = tid; i < 128 * 32; i += 256) {
        int m = i >> 5, kp = i & 31;
        int row = bm + m;
        float2 v = make_float2(0.f, 0.f);
        if (row < NN) v = *(const float2*)(g_x + (size_t)row * DIM + kp * 2);
        *(__half2*)&sA[m * ASTR + kp * 2] = __floats2half2_rn(v.x, v.y);
    }

    int wid = tid >> 5, lane = tid & 31;
    int wm = wid >> 1, wn = wid & 1;     // 4x2 warps, warp tile 32x32
    int gq = lane >> 2, tq = lane & 3;

    for (int nc = 0; nc < 8; nc++) {
        int bc = nc * 64;
        __syncthreads();   // iter0: publish A; later: protect B reuse
        // B chunk: 64 cols x 64 k
        for (int i = tid; i < 64 * 32; i += 256) {
            int n = i >> 5, kp = i & 31;
            size_t go = (size_t)(bc + n) * 64 + kp * 2;
            *(u32*)&sB[n * ASTR + kp * 2] = *(const u32*)(Wh + go);
        }
        __syncthreads();

        float C[2][4][4];
#pragma unroll
        for (int i = 0; i < 2; i++)
#pragma unroll
            for (int j = 0; j < 4; j++)
#pragma unroll
                for (int q = 0; q < 4; q++) C[i][j][q] = 0.f;

#pragma unroll
        for (int kk = 0; kk < 4; kk++) {
            int k0 = kk * 16 + tq * 2;
            u32 a[2][4];
#pragma unroll
            for (int i = 0; i < 2; i++) {
                int r = wm * 32 + i * 16 + gq;
                a[i][0] = *(const u32*)&sA[r * ASTR + k0];
                a[i][1] = *(const u32*)&sA[(r + 8) * ASTR + k0];
                a[i][2] = *(const u32*)&sA[r * ASTR + k0 + 8];
                a[i][3] = *(const u32*)&sA[(r + 8) * ASTR + k0 + 8];
            }
            u32 b[4][2];
#pragma unroll
            for (int j = 0; j < 4; j++) {
                int c = wn * 32 + j * 8 + gq;
                b[j][0] = *(const u32*)&sB[c * ASTR + k0];
                b[j][1] = *(const u32*)&sB[c * ASTR + k0 + 8];
            }
#pragma unroll
            for (int i = 0; i < 2; i++)
#pragma unroll
                for (int j = 0; j < 4; j++)
                    mma16816(C[i][j], a[i][0], a[i][1], a[i][2], a[i][3], b[j][0], b[j][1]);
        }

        // epilogue: bias + fp16 store this 64-col chunk
#pragma unroll
        for (int j = 0; j < 4; j++) {
            int col = bc + wn * 32 + j * 8 + tq * 2;   // 0..511
            __half* base; const float* bias;
            if (col < 256) { base = g_xl16; bias = bl; }
            else           { base = g_xr16; bias = br; col -= 256; }
            float b0 = bias[col], b1 = bias[col + 1];
#pragma unroll
            for (int i = 0; i < 2; i++) {
                int r0 = bm + wm * 32 + i * 16 + gq;
                if (r0 < NN)
                    *(__half2*)(base + (size_t)r0 * HD + col) =
                        __floats2half2_rn(C[i][j][0] + b0, C[i][j][1] + b1);
                int r1 = r0 + 8;
                if (r1 < NN)
                    *(__half2*)(base + (size_t)r1 * HD + col) =
                        __floats2half2_rn(C[i][j][2] + b0, C[i][j][3] + b1);
            }
        }
    }
}

// ---------------- fused attention --------------------------------------------
__device__ __forceinline__ float lrelu(float v) { return v > 0.f ? v : 0.2f * v; }

// unpack 8 halfs (uint4) -> two float4
__device__ __forceinline__ void h8f(uint4 v, float4& a, float4& b) {
    __half2* h = (__half2*)&v;
    float2 f0 = __half22float2(h[0]);
    float2 f1 = __half22float2(h[1]);
    float2 f2 = __half22float2(h[2]);
    float2 f3 = __half22float2(h[3]);
    a = make_float4(f0.x, f0.y, f1.x, f1.y);
    b = make_float4(f2.x, f2.y, f3.x, f3.y);
}

__device__ __forceinline__ float edge_score(float4 ta, float4 tb,
                                            float4 xra, float4 xrb,
                                            float4 ata, float4 atb) {
    float p = lrelu(ta.x + xra.x) * ata.x + lrelu(ta.y + xra.y) * ata.y
            + lrelu(ta.z + xra.z) * ata.z + lrelu(ta.w + xra.w) * ata.w
            + lrelu(tb.x + xrb.x) * atb.x + lrelu(tb.y + xrb.y) * atb.y
            + lrelu(tb.z + xrb.z) * atb.z + lrelu(tb.w + xrb.w) * atb.w;
    p += __shfl_xor_sync(0xffffffffu, p, 1);
    p += __shfl_xor_sync(0xffffffffu, p, 2);
    p += __shfl_xor_sync(0xffffffffu, p, 4);
    return p;
}

// one warp per destination node; lane owns halfs [8*lane, 8*lane+8) (one uint4)
// dopool: last layer adds result straight into g_pool/g_cnt (no g_x store)
__global__ __launch_bounds__(256) void k_attn(const float* __restrict__ att,
                                              const float* __restrict__ gb, int dogelu,
                                              const int* __restrict__ batch, int dopool) {
    int w = (blockIdx.x * blockDim.x + threadIdx.x) >> 5;
    int lane = threadIdx.x & 31;
    if (w >= NN) return;

    float4 xra, xrb;
    h8f(*(const uint4*)(g_xr16 + (size_t)w * HD + lane * 8), xra, xrb);
    const float4* at4 = (const float4*)att;
    float4 ata = at4[2 * lane], atb = at4[2 * lane + 1];

    float4 sa, sb;
    h8f(*(const uint4*)(g_xl16 + (size_t)w * HD + lane * 8), sa, sb);

    int beg = g_rowptr[w], end = g_rowptr[w + 1];
    int j = beg;
    bool have = (j < end);
    int snext = (j + 1 < end) ? g_csrc[j + 1] : 0;
    uint4 nv;
    if (have) {
        int s = g_csrc[j];
        nv = *(const uint4*)(g_xl16 + (size_t)s * HD + lane * 8);
    }

    float denom;
    float acc[8];
    {   // self-loop edge
        float e = edge_score(sa, sb, xra, xrb, ata, atb);
        float ea = __expf(e);
        denom = ea;
        acc[0] = ea * sa.x; acc[1] = ea * sa.y; acc[2] = ea * sa.z; acc[3] = ea * sa.w;
        acc[4] = ea * sb.x; acc[5] = ea * sb.y; acc[6] = ea * sb.z; acc[7] = ea * sb.w;
    }
    while (have) {
        float4 ta, tb;
        h8f(nv, ta, tb);
        j++;
        have = (j < end);
        int s = snext;
        snext = (j + 1 < end) ? g_csrc[j + 1] : 0;
        if (have) nv = *(const uint4*)(g_xl16 + (size_t)s * HD + lane * 8);

        float e = edge_score(ta, tb, xra, xrb, ata, atb);
        float ea = __expf(e);
        denom += ea;
        acc[0] += ea * ta.x; acc[1] += ea * ta.y; acc[2] += ea * ta.z; acc[3] += ea * ta.w;
        acc[4] += ea * tb.x; acc[5] += ea * tb.y; acc[6] += ea * tb.z; acc[7] += ea * tb.w;
    }

    float inv = 1.f / denom;
    float r[8];
#pragma unroll
    for (int c = 0; c < 8; c++) {
        float v = acc[c] * inv;
        v += __shfl_xor_sync(0xffffffffu, v, 8);
        v += __shfl_xor_sync(0xffffffffu, v, 16);
        v *= 0.25f;
        r[c] = v;
    }
    int d0 = 8 * (lane & 7);
#pragma unroll
    for (int c = 0; c < 8; c++) {
        float s = r[c] + gb[d0 + c];
        if (dogelu) s = 0.5f * s * (1.f + erff(s * 0.70710678118654752f));
        r[c] = s;
    }
    if (dopool) {
        int gix = batch[w];
        if (lane < 8) {
            float* p = g_pool + (size_t)gix * DIM + d0;
#pragma unroll
            for (int c = 0; c < 8; c++) atomicAdd(&p[c], r[c]);
        }
        if (lane == 0) atomicAdd(&g_cnt[gix], 1.f);
    } else if (lane < 8) {
        *(float4*)(g_x + (size_t)w * DIM + d0)     = make_float4(r[0], r[1], r[2], r[3]);
        *(float4*)(g_x + (size_t)w * DIM + d0 + 4) = make_float4(r[4], r[5], r[6], r[7]);
    }
}

// ---------------- head -------------------------------------------------------
__global__ void k_final(const float* __restrict__ Wc, const float* __restrict__ bc,
                        float* __restrict__ out) {
    int g = blockIdx.x;
    int lane = threadIdx.x;
    float inv = 1.f / fmaxf(g_cnt[g], 1.f);
    float p0 = g_pool[g * DIM + lane] * inv;
    float p1 = g_pool[g * DIM + 32 + lane] * inv;
#pragma unroll
    for (int c = 0; c < NC; c++) {
        float s = p0 * Wc[lane * NC + c] + p1 * Wc[(lane + 32) * NC + c];
#pragma unroll
        for (int o = 16; o; o >>= 1) s += __shfl_xor_sync(0xffffffffu, s, o);
        if (lane == 0) out[g * NC + c] = s + bc[c];
    }
}

// ---------------- launch ------------------------------------------------------
extern "C" void kernel_launch(void* const* d_in, const int* in_sizes, int n_in,
                              void* d_out, int out_size) {
    (void)in_sizes; (void)n_in; (void)out_size;
    const int*   feat  = (const int*)  d_in[0];
    const int*   econ  = (const int*)  d_in[1];
    const int*   batch = (const int*)  d_in[2];
    const float* emb   = (const float*)d_in[3];
    const float* Wl    = (const float*)d_in[4];
    const float* bl    = (const float*)d_in[5];
    const float* Wr    = (const float*)d_in[6];
    const float* br    = (const float*)d_in[7];
    const float* att   = (const float*)d_in[8];
    const float* gbias = (const float*)d_in[9];
    const float* Wc    = (const float*)d_in[10];
    const float* bcv   = (const float*)d_in[11];
    float* out = (float*)d_out;

    const int* src = econ;
    const int* dst = econ + EDG;

    cudaFuncSetAttribute(k_gemm_mma, cudaFuncAttributeMaxDynamicSharedMemorySize, GSMEM);

    k_encoder<<<(NN * DIM + 255) / 256, 256>>>(feat, emb, Wl, Wr);

    k_hist<<<(EDG + 255) / 256, 256>>>(dst);
    k_scanA<<<NSB, SCAN_B>>>();
    k_scanB<<<1, 64>>>();
    k_scanC<<<(NN + 255) / 256, 256>>>();
    k_scatter<<<(EDG + 255) / 256, 256>>>(src, dst);

    for (int l = 0; l < NL; l++) {
        k_gemm_mma<<<(NN + 127) / 128, 256, GSMEM>>>(l, bl + l * HD, br + l * HD);
        k_attn<<<(NN * 32 + 255) / 256, 256>>>(att + l * NH * DIM, gbias + l * DIM,
                                               (l < NL - 1) ? 1 : 0,
                                               batch, (l == NL - 1) ? 1 : 0);
    }

    k_final<<<NG, 32>>>(Wc, bcv, out);
}

// round 16
// speedup vs baseline: 1.2113x; 1.0598x over previous
#include <cuda_runtime.h>
#include <cuda_fp16.h>
#include <math.h>
#include <cstdint>

#define NN 50000
#define EDG 400000
#define DIM 64
#define NH 4
#define HD 256
#define NL 3
#define NC 10
#define NG 512
#define SCAN_B 1024
#define NSB ((NN + SCAN_B - 1) / SCAN_B)

typedef unsigned long long u64;
typedef unsigned int u32;

// ---------------- scratch ----------------------------------------------------
__device__ __align__(16) float g_x[NN * DIM];
__device__ __align__(16) __half g_xl16[NN * HD];   // fp16: attention-only consumers
__device__ __align__(16) __half g_xr16[NN * HD];
__device__ int   g_deg[NN];
__device__ int   g_rowptr[NN + 1];
__device__ int   g_cursor[NN];
__device__ int   g_csrc[EDG];
__device__ int   g_bsum[64];
__device__ int   g_boff[64];
__device__ float g_pool[NG * DIM];
__device__ float g_cnt[NG];
// W fp16 image: [L][n=512][k=64], n over [Wl | Wr] columns
__device__ __align__(16) __half g_wh[NL * 512 * 64];

// ---------------- atom encoder (+ scratch zero + wprep fused) -----------------
__global__ void k_encoder(const int* __restrict__ feat, const float* __restrict__ emb,
                          const float* __restrict__ Wl, const float* __restrict__ Wr) {
    int t = blockIdx.x * blockDim.x + threadIdx.x;
    if (t < NN) g_deg[t] = 0;
    if (t < NG * DIM) g_pool[t] = 0.f;
    if (t < NG) g_cnt[t] = 0.f;
    // fused wprep: W -> fp16 image [l][n][k]
    if (t < NL * 512 * 32) {
        int kp = t & 31;
        int n = (t >> 5) & 511;
        int l = t >> 14;
        int k0 = kp * 2;
        const float* W = (n < 256) ? Wl : Wr;
        int nn = n & 255;
        float w0 = W[(l * 64 + k0) * 256 + nn];
        float w1 = W[(l * 64 + k0 + 1) * 256 + nn];
        *(__half2*)(g_wh + (size_t)l * 32768 + n * 64 + k0) = __floats2half2_rn(w0, w1);
    }
    if (t >= NN * DIM) return;
    int n = t >> 6, d = t & 63;
    const int offs[9] = {0, 119, 124, 136, 148, 158, 164, 170, 172};
    float s = 0.f;
#pragma unroll
    for (int j = 0; j < 9; j++) {
        int idx = feat[n * 9 + j] + offs[j];
        s += emb[idx * DIM + d];
    }
    g_x[t] = s;
}

// ---------------- CSR build --------------------------------------------------
__global__ void k_hist(const int* __restrict__ dst) {
    int e = blockIdx.x * blockDim.x + threadIdx.x;
    if (e < EDG) atomicAdd(&g_deg[dst[e]], 1);
}
__global__ __launch_bounds__(SCAN_B) void k_scanA() {
    __shared__ int sh[SCAN_B];
    int b = blockIdx.x, t = threadIdx.x;
    int i = b * SCAN_B + t;
    int v = (i < NN) ? g_deg[i] : 0;
    sh[t] = v;
    __syncthreads();
    for (int o = 1; o < SCAN_B; o <<= 1) {
        int u = (t >= o) ? sh[t - o] : 0;
        __syncthreads();
        sh[t] += u;
        __syncthreads();
    }
    if (i < NN) g_rowptr[i] = sh[t] - v;
    if (t == SCAN_B - 1) g_bsum[b] = sh[t];
}
__global__ void k_scanB() {
    __shared__ int sh[64];
    int t = threadIdx.x;
    int v = (t < NSB) ? g_bsum[t] : 0;
    sh[t] = v;
    __syncthreads();
    for (int o = 1; o < 64; o <<= 1) {
        int u = (t >= o) ? sh[t - o] : 0;
        __syncthreads();
        sh[t] += u;
        __syncthreads();
    }
    g_boff[t] = sh[t] - v;
    if (t == NSB - 1) g_rowptr[NN] = sh[t];
}
__global__ void k_scanC() {
    int i = blockIdx.x * blockDim.x + threadIdx.x;
    if (i < NN) {
        int r = g_rowptr[i] + g_boff[i / SCAN_B];
        g_rowptr[i] = r;
        g_cursor[i] = r;
    }
}
__global__ void k_scatter(const int* __restrict__ src, const int* __restrict__ dst) {
    int e = blockIdx.x * blockDim.x + threadIdx.x;
    if (e < EDG) {
        int d = dst[e];
        int pos = atomicAdd(&g_cursor[d], 1);
        g_csrc[pos] = src[e];
    }
}

// ---------------- HMMA GEMM: [xl|xr] = x @ [Wl|Wr] + bias (fp16 in/out) -------
// CTA: 128 rows, loops over 8 column-chunks of 64. Dynamic smem 27,648B.
// 8 warps (4m x 2n), warp tile 32x32. Single-pass fp16 MMA, fp32 accumulate.
// DO NOT widen the N warp tile (32x64 regressed twice: R10, R14 — reg pressure).
#define ASTR 72
#define GSMEM ((128 * ASTR + 64 * ASTR) * 2)   // 27648 bytes

__device__ __forceinline__ void mma16816(float c[4], u32 a0, u32 a1, u32 a2, u32 a3,
                                         u32 b0, u32 b1) {
    asm volatile("mma.sync.aligned.m16n8k16.row.col.f32.f16.f16.f32 "
                 "{%0,%1,%2,%3}, {%4,%5,%6,%7}, {%8,%9}, {%0,%1,%2,%3};"
                 : "+f"(c[0]), "+f"(c[1]), "+f"(c[2]), "+f"(c[3])
                 : "r"(a0), "r"(a1), "r"(a2), "r"(a3), "r"(b0), "r"(b1));
}

__global__ __launch_bounds__(256) void k_gemm_mma(int layer,
                                                  const float* __restrict__ bl,
                                                  const float* __restrict__ br) {
    extern __shared__ __half smem[];
    __half* sA = smem;                 // 128*ASTR
    __half* sB = sA + 128 * ASTR;      // 64*ASTR

    const __half* Wh = g_wh + (size_t)layer * 32768;

    int tid = threadIdx.x;
    int bm = blockIdx.x * 128;

    // A: 128x64 fp32 -> fp16 (once per CTA)
    for (int i = tid; i < 128 * 32; i += 256) {
        int m = i >> 5, kp = i & 31;
        int row = bm + m;
        float2 v = make_float2(0.f, 0.f);
        if (row < NN) v = *(const float2*)(g_x + (size_t)row * DIM + kp * 2);
        *(__half2*)&sA[m * ASTR + kp * 2] = __floats2half2_rn(v.x, v.y);
    }

    int wid = tid >> 5, lane = tid & 31;
    int wm = wid >> 1, wn = wid & 1;     // 4x2 warps, warp tile 32x32
    int gq = lane >> 2, tq = lane & 3;

    for (int nc = 0; nc < 8; nc++) {
        int bc = nc * 64;
        __syncthreads();   // iter0: publish A; later: protect B reuse
        // B chunk: 64 cols x 64 k
        for (int i = tid; i < 64 * 32; i += 256) {
            int n = i >> 5, kp = i & 31;
            size_t go = (size_t)(bc + n) * 64 + kp * 2;
            *(u32*)&sB[n * ASTR + kp * 2] = *(const u32*)(Wh + go);
        }
        __syncthreads();

        float C[2][4][4];
#pragma unroll
        for (int i = 0; i < 2; i++)
#pragma unroll
            for (int j = 0; j < 4; j++)
#pragma unroll
                for (int q = 0; q < 4; q++) C[i][j][q] = 0.f;

#pragma unroll
        for (int kk = 0; kk < 4; kk++) {
            int k0 = kk * 16 + tq * 2;
            u32 a[2][4];
#pragma unroll
            for (int i = 0; i < 2; i++) {
                int r = wm * 32 + i * 16 + gq;
                a[i][0] = *(const u32*)&sA[r * ASTR + k0];
                a[i][1] = *(const u32*)&sA[(r + 8) * ASTR + k0];
                a[i][2] = *(const u32*)&sA[r * ASTR + k0 + 8];
                a[i][3] = *(const u32*)&sA[(r + 8) * ASTR + k0 + 8];
            }
            u32 b[4][2];
#pragma unroll
            for (int j = 0; j < 4; j++) {
                int c = wn * 32 + j * 8 + gq;
                b[j][0] = *(const u32*)&sB[c * ASTR + k0];
                b[j][1] = *(const u32*)&sB[c * ASTR + k0 + 8];
            }
#pragma unroll
            for (int i = 0; i < 2; i++)
#pragma unroll
                for (int j = 0; j < 4; j++)
                    mma16816(C[i][j], a[i][0], a[i][1], a[i][2], a[i][3], b[j][0], b[j][1]);
        }

        // epilogue: bias + fp16 store this 64-col chunk
#pragma unroll
        for (int j = 0; j < 4; j++) {
            int col = bc + wn * 32 + j * 8 + tq * 2;   // 0..511
            __half* base; const float* bias;
            if (col < 256) { base = g_xl16; bias = bl; }
            else           { base = g_xr16; bias = br; col -= 256; }
            float b0 = bias[col], b1 = bias[col + 1];
#pragma unroll
            for (int i = 0; i < 2; i++) {
                int r0 = bm + wm * 32 + i * 16 + gq;
                if (r0 < NN)
                    *(__half2*)(base + (size_t)r0 * HD + col) =
                        __floats2half2_rn(C[i][j][0] + b0, C[i][j][1] + b1);
                int r1 = r0 + 8;
                if (r1 < NN)
                    *(__half2*)(base + (size_t)r1 * HD + col) =
                        __floats2half2_rn(C[i][j][2] + b0, C[i][j][3] + b1);
            }
        }
    }
}

// ---------------- fused attention --------------------------------------------
__device__ __forceinline__ float lrelu(float v) { return v > 0.f ? v : 0.2f * v; }

// unpack 8 halfs (uint4) -> two float4
__device__ __forceinline__ void h8f(uint4 v, float4& a, float4& b) {
    __half2* h = (__half2*)&v;
    float2 f0 = __half22float2(h[0]);
    float2 f1 = __half22float2(h[1]);
    float2 f2 = __half22float2(h[2]);
    float2 f3 = __half22float2(h[3]);
    a = make_float4(f0.x, f0.y, f1.x, f1.y);
    b = make_float4(f2.x, f2.y, f3.x, f3.y);
}

__device__ __forceinline__ float edge_score(float4 ta, float4 tb,
                                            float4 xra, float4 xrb,
                                            float4 ata, float4 atb) {
    float p = lrelu(ta.x + xra.x) * ata.x + lrelu(ta.y + xra.y) * ata.y
            + lrelu(ta.z + xra.z) * ata.z + lrelu(ta.w + xra.w) * ata.w
            + lrelu(tb.x + xrb.x) * atb.x + lrelu(tb.y + xrb.y) * atb.y
            + lrelu(tb.z + xrb.z) * atb.z + lrelu(tb.w + xrb.w) * atb.w;
    p += __shfl_xor_sync(0xffffffffu, p, 1);
    p += __shfl_xor_sync(0xffffffffu, p, 2);
    p += __shfl_xor_sync(0xffffffffu, p, 4);
    return p;
}

// one warp per destination node; lane owns halfs [8*lane, 8*lane+8) (one uint4)
__global__ __launch_bounds__(256) void k_attn(const float* __restrict__ att,
                                              const float* __restrict__ gb, int dogelu) {
    int w = (blockIdx.x * blockDim.x + threadIdx.x) >> 5;
    int lane = threadIdx.x & 31;
    if (w >= NN) return;

    float4 xra, xrb;
    h8f(*(const uint4*)(g_xr16 + (size_t)w * HD + lane * 8), xra, xrb);
    const float4* at4 = (const float4*)att;
    float4 ata = at4[2 * lane], atb = at4[2 * lane + 1];

    float4 sa, sb;
    h8f(*(const uint4*)(g_xl16 + (size_t)w * HD + lane * 8), sa, sb);

    int beg = g_rowptr[w], end = g_rowptr[w + 1];
    int j = beg;
    bool have = (j < end);
    int snext = (j + 1 < end) ? g_csrc[j + 1] : 0;
    uint4 nv;
    if (have) {
        int s = g_csrc[j];
        nv = *(const uint4*)(g_xl16 + (size_t)s * HD + lane * 8);
    }

    float denom;
    float acc[8];
    {   // self-loop edge
        float e = edge_score(sa, sb, xra, xrb, ata, atb);
        float ea = __expf(e);
        denom = ea;
        acc[0] = ea * sa.x; acc[1] = ea * sa.y; acc[2] = ea * sa.z; acc[3] = ea * sa.w;
        acc[4] = ea * sb.x; acc[5] = ea * sb.y; acc[6] = ea * sb.z; acc[7] = ea * sb.w;
    }
    while (have) {
        float4 ta, tb;
        h8f(nv, ta, tb);
        j++;
        have = (j < end);
        int s = snext;
        snext = (j + 1 < end) ? g_csrc[j + 1] : 0;
        if (have) nv = *(const uint4*)(g_xl16 + (size_t)s * HD + lane * 8);

        float e = edge_score(ta, tb, xra, xrb, ata, atb);
        float ea = __expf(e);
        denom += ea;
        acc[0] += ea * ta.x; acc[1] += ea * ta.y; acc[2] += ea * ta.z; acc[3] += ea * ta.w;
        acc[4] += ea * tb.x; acc[5] += ea * tb.y; acc[6] += ea * tb.z; acc[7] += ea * tb.w;
    }

    float inv = 1.f / denom;
    float r[8];
#pragma unroll
    for (int c = 0; c < 8; c++) {
        float v = acc[c] * inv;
        v += __shfl_xor_sync(0xffffffffu, v, 8);
        v += __shfl_xor_sync(0xffffffffu, v, 16);
        v *= 0.25f;
        r[c] = v;
    }
    int d0 = 8 * (lane & 7);
#pragma unroll
    for (int c = 0; c < 8; c++) {
        float s = r[c] + gb[d0 + c];
        if (dogelu) s = 0.5f * s * (1.f + erff(s * 0.70710678118654752f));
        r[c] = s;
    }
    if (lane < 8) {
        *(float4*)(g_x + (size_t)w * DIM + d0)     = make_float4(r[0], r[1], r[2], r[3]);
        *(float4*)(g_x + (size_t)w * DIM + d0 + 4) = make_float4(r[4], r[5], r[6], r[7]);
    }
}

// ---------------- pool + head ------------------------------------------------
__global__ void k_pool(const int* __restrict__ batch) {
    int t = blockIdx.x * blockDim.x + threadIdx.x;
    if (t >= NN * DIM) return;
    int n = t >> 6, d = t & 63;
    int gidx = batch[n];
    atomicAdd(&g_pool[gidx * DIM + d], g_x[t]);
    if (d == 0) atomicAdd(&g_cnt[gidx], 1.f);
}
__global__ void k_final(const float* __restrict__ Wc, const float* __restrict__ bc,
                        float* __restrict__ out) {
    int g = blockIdx.x;
    int lane = threadIdx.x;
    float inv = 1.f / fmaxf(g_cnt[g], 1.f);
    float p0 = g_pool[g * DIM + lane] * inv;
    float p1 = g_pool[g * DIM + 32 + lane] * inv;
#pragma unroll
    for (int c = 0; c < NC; c++) {
        float s = p0 * Wc[lane * NC + c] + p1 * Wc[(lane + 32) * NC + c];
#pragma unroll
        for (int o = 16; o; o >>= 1) s += __shfl_xor_sync(0xffffffffu, s, o);
        if (lane == 0) out[g * NC + c] = s + bc[c];
    }
}

// ---------------- launch ------------------------------------------------------
extern "C" void kernel_launch(void* const* d_in, const int* in_sizes, int n_in,
                              void* d_out, int out_size) {
    (void)in_sizes; (void)n_in; (void)out_size;
    const int*   feat  = (const int*)  d_in[0];
    const int*   econ  = (const int*)  d_in[1];
    const int*   batch = (const int*)  d_in[2];
    const float* emb   = (const float*)d_in[3];
    const float* Wl    = (const float*)d_in[4];
    const float* bl    = (const float*)d_in[5];
    const float* Wr    = (const float*)d_in[6];
    const float* br    = (const float*)d_in[7];
    const float* att   = (const float*)d_in[8];
    const float* gbias = (const float*)d_in[9];
    const float* Wc    = (const float*)d_in[10];
    const float* bcv   = (const float*)d_in[11];
    float* out = (float*)d_out;

    const int* src = econ;
    const int* dst = econ + EDG;

    cudaFuncSetAttribute(k_gemm_mma, cudaFuncAttributeMaxDynamicSharedMemorySize, GSMEM);

    k_encoder<<<(NN * DIM + 255) / 256, 256>>>(feat, emb, Wl, Wr);

    k_hist<<<(EDG + 255) / 256, 256>>>(dst);
    k_scanA<<<NSB, SCAN_B>>>();
    k_scanB<<<1, 64>>>();
    k_scanC<<<(NN + 255) / 256, 256>>>();
    k_scatter<<<(EDG + 255) / 256, 256>>>(src, dst);

    for (int l = 0; l < NL; l++) {
        k_gemm_mma<<<(NN + 127) / 128, 256, GSMEM>>>(l, bl + l * HD, br + l * HD);
        k_attn<<<(NN * 32 + 255) / 256, 256>>>(att + l * NH * DIM, gbias + l * DIM,
                                               (l < NL - 1) ? 1 : 0);
    }

    k_pool<<<(NN * DIM + 255) / 256, 256>>>(batch);
    k_final<<<NG, 32>>>(Wc, bcv, out);
}

// round 17
// speedup vs baseline: 1.2446x; 1.0275x over previous
#include <cuda_runtime.h>
#include <cuda_fp16.h>
#include <math.h>
#include <cstdint>

#define NN 50000
#define EDG 400000
#define DIM 64
#define NH 4
#define HD 256
#define NL 3
#define NC 10
#define NG 512
#define SCAN_B 1024
#define NSB ((NN + SCAN_B - 1) / SCAN_B)

typedef unsigned long long u64;
typedef unsigned int u32;

// ---------------- scratch ----------------------------------------------------
__device__ __align__(16) float g_x[NN * DIM];
__device__ __align__(16) __half g_xl16[NN * HD];   // fp16: attention-only consumers
__device__ __align__(16) __half g_xr16[NN * HD];
__device__ int   g_deg[NN];
__device__ int   g_rowptr[NN + 1];
__device__ int   g_cursor[NN];
__device__ int   g_csrc[EDG];
__device__ int   g_bsum[64];
__device__ int   g_boff[64];
__device__ float g_pool[NG * DIM];
__device__ float g_cnt[NG];
// W fp16 image: [L][n=512][k=64], n over [Wl | Wr] columns
__device__ __align__(16) __half g_wh[NL * 512 * 64];

// ---------------- atom encoder (+ pool zero + wprep fused) --------------------
__global__ void k_encoder(const int* __restrict__ feat, const float* __restrict__ emb,
                          const float* __restrict__ Wl, const float* __restrict__ Wr) {
    int t = blockIdx.x * blockDim.x + threadIdx.x;
    if (t < NG * DIM) g_pool[t] = 0.f;
    if (t < NG) g_cnt[t] = 0.f;
    // fused wprep: W -> fp16 image [l][n][k]
    if (t < NL * 512 * 32) {
        int kp = t & 31;
        int n = (t >> 5) & 511;
        int l = t >> 14;
        int k0 = kp * 2;
        const float* W = (n < 256) ? Wl : Wr;
        int nn = n & 255;
        float w0 = W[(l * 64 + k0) * 256 + nn];
        float w1 = W[(l * 64 + k0 + 1) * 256 + nn];
        *(__half2*)(g_wh + (size_t)l * 32768 + n * 64 + k0) = __floats2half2_rn(w0, w1);
    }
    if (t >= NN * DIM) return;
    int n = t >> 6, d = t & 63;
    const int offs[9] = {0, 119, 124, 136, 148, 158, 164, 170, 172};
    float s = 0.f;
#pragma unroll
    for (int j = 0; j < 9; j++) {
        int idx = feat[n * 9 + j] + offs[j];
        s += emb[idx * DIM + d];
    }
    g_x[t] = s;
}

// ---------------- CSR build (runs on side stream) -----------------------------
__global__ void k_zerodeg() {
    int t = blockIdx.x * blockDim.x + threadIdx.x;
    if (t < NN) g_deg[t] = 0;
}
__global__ void k_hist(const int* __restrict__ dst) {
    int e = blockIdx.x * blockDim.x + threadIdx.x;
    if (e < EDG) atomicAdd(&g_deg[dst[e]], 1);
}
__global__ __launch_bounds__(SCAN_B) void k_scanA() {
    __shared__ int sh[SCAN_B];
    int b = blockIdx.x, t = threadIdx.x;
    int i = b * SCAN_B + t;
    int v = (i < NN) ? g_deg[i] : 0;
    sh[t] = v;
    __syncthreads();
    for (int o = 1; o < SCAN_B; o <<= 1) {
        int u = (t >= o) ? sh[t - o] : 0;
        __syncthreads();
        sh[t] += u;
        __syncthreads();
    }
    if (i < NN) g_rowptr[i] = sh[t] - v;
    if (t == SCAN_B - 1) g_bsum[b] = sh[t];
}
__global__ void k_scanB() {
    __shared__ int sh[64];
    int t = threadIdx.x;
    int v = (t < NSB) ? g_bsum[t] : 0;
    sh[t] = v;
    __syncthreads();
    for (int o = 1; o < 64; o <<= 1) {
        int u = (t >= o) ? sh[t - o] : 0;
        __syncthreads();
        sh[t] += u;
        __syncthreads();
    }
    g_boff[t] = sh[t] - v;
    if (t == NSB - 1) g_rowptr[NN] = sh[t];
}
__global__ void k_scanC() {
    int i = blockIdx.x * blockDim.x + threadIdx.x;
    if (i < NN) {
        int r = g_rowptr[i] + g_boff[i / SCAN_B];
        g_rowptr[i] = r;
        g_cursor[i] = r;
    }
}
__global__ void k_scatter(const int* __restrict__ src, const int* __restrict__ dst) {
    int e = blockIdx.x * blockDim.x + threadIdx.x;
    if (e < EDG) {
        int d = dst[e];
        int pos = atomicAdd(&g_cursor[d], 1);
        g_csrc[pos] = src[e];
    }
}

// ---------------- HMMA GEMM: [xl|xr] = x @ [Wl|Wr] + bias (fp16 in/out) -------
// CTA: 128 rows, loops over 8 column-chunks of 64. Dynamic smem 27,648B.
// 8 warps (4m x 2n), warp tile 32x32. Single-pass fp16 MMA, fp32 accumulate.
// DO NOT widen the N warp tile (32x64 regressed twice: R10, R14 — reg pressure).
#define ASTR 72
#define GSMEM ((128 * ASTR + 64 * ASTR) * 2)   // 27648 bytes

__device__ __forceinline__ void mma16816(float c[4], u32 a0, u32 a1, u32 a2, u32 a3,
                                         u32 b0, u32 b1) {
    asm volatile("mma.sync.aligned.m16n8k16.row.col.f32.f16.f16.f32 "
                 "{%0,%1,%2,%3}, {%4,%5,%6,%7}, {%8,%9}, {%0,%1,%2,%3};"
                 : "+f"(c[0]), "+f"(c[1]), "+f"(c[2]), "+f"(c[3])
                 : "r"(a0), "r"(a1), "r"(a2), "r"(a3), "r"(b0), "r"(b1));
}

__global__ __launch_bounds__(256) void k_gemm_mma(int layer,
                                                  const float* __restrict__ bl,
                                                  const float* __restrict__ br) {
    extern __shared__ __half smem[];
    __half* sA = smem;                 // 128*ASTR
    __half* sB = sA + 128 * ASTR;      // 64*ASTR

    const __half* Wh = g_wh + (size_t)layer * 32768;

    int tid = threadIdx.x;
    int bm = blockIdx.x * 128;

    // A: 128x64 fp32 -> fp16 (once per CTA)
    for (int i = tid; i < 128 * 32; i += 256) {
        int m = i >> 5, kp = i & 31;
        int row = bm + m;
        float2 v = make_float2(0.f, 0.f);
        if (row < NN) v = *(const float2*)(g_x + (size_t)row * DIM + kp * 2);
        *(__half2*)&sA[m * ASTR + kp * 2] = __floats2half2_rn(v.x, v.y);
    }

    int wid = tid >> 5, lane = tid & 31;
    int wm = wid >> 1, wn = wid & 1;     // 4x2 warps, warp tile 32x32
    int gq = lane >> 2, tq = lane & 3;

    for (int nc = 0; nc < 8; nc++) {
        int bc = nc * 64;
        __syncthreads();   // iter0: publish A; later: protect B reuse
        // B chunk: 64 cols x 64 k
        for (int i = tid; i < 64 * 32; i += 256) {
            int n = i >> 5, kp = i & 31;
            size_t go = (size_t)(bc + n) * 64 + kp * 2;
            *(u32*)&sB[n * ASTR + kp * 2] = *(const u32*)(Wh + go);
        }
        __syncthreads();

        float C[2][4][4];
#pragma unroll
        for (int i = 0; i < 2; i++)
#pragma unroll
            for (int j = 0; j < 4; j++)
#pragma unroll
                for (int q = 0; q < 4; q++) C[i][j][q] = 0.f;

#pragma unroll
        for (int kk = 0; kk < 4; kk++) {
            int k0 = kk * 16 + tq * 2;
            u32 a[2][4];
#pragma unroll
            for (int i = 0; i < 2; i++) {
                int r = wm * 32 + i * 16 + gq;
                a[i][0] = *(const u32*)&sA[r * ASTR + k0];
                a[i][1] = *(const u32*)&sA[(r + 8) * ASTR + k0];
                a[i][2] = *(const u32*)&sA[r * ASTR + k0 + 8];
                a[i][3] = *(const u32*)&sA[(r + 8) * ASTR + k0 + 8];
            }
            u32 b[4][2];
#pragma unroll
            for (int j = 0; j < 4; j++) {
                int c = wn * 32 + j * 8 + gq;
                b[j][0] = *(const u32*)&sB[c * ASTR + k0];
                b[j][1] = *(const u32*)&sB[c * ASTR + k0 + 8];
            }
#pragma unroll
            for (int i = 0; i < 2; i++)
#pragma unroll
                for (int j = 0; j < 4; j++)
                    mma16816(C[i][j], a[i][0], a[i][1], a[i][2], a[i][3], b[j][0], b[j][1]);
        }

        // epilogue: bias + fp16 store this 64-col chunk
#pragma unroll
        for (int j = 0; j < 4; j++) {
            int col = bc + wn * 32 + j * 8 + tq * 2;   // 0..511
            __half* base; const float* bias;
            if (col < 256) { base = g_xl16; bias = bl; }
            else           { base = g_xr16; bias = br; col -= 256; }
            float b0 = bias[col], b1 = bias[col + 1];
#pragma unroll
            for (int i = 0; i < 2; i++) {
                int r0 = bm + wm * 32 + i * 16 + gq;
                if (r0 < NN)
                    *(__half2*)(base + (size_t)r0 * HD + col) =
                        __floats2half2_rn(C[i][j][0] + b0, C[i][j][1] + b1);
                int r1 = r0 + 8;
                if (r1 < NN)
                    *(__half2*)(base + (size_t)r1 * HD + col) =
                        __floats2half2_rn(C[i][j][2] + b0, C[i][j][3] + b1);
            }
        }
    }
}

// ---------------- fused attention --------------------------------------------
__device__ __forceinline__ float lrelu(float v) { return v > 0.f ? v : 0.2f * v; }

// unpack 8 halfs (uint4) -> two float4
__device__ __forceinline__ void h8f(uint4 v, float4& a, float4& b) {
    __half2* h = (__half2*)&v;
    float2 f0 = __half22float2(h[0]);
    float2 f1 = __half22float2(h[1]);
    float2 f2 = __half22float2(h[2]);
    float2 f3 = __half22float2(h[3]);
    a = make_float4(f0.x, f0.y, f1.x, f1.y);
    b = make_float4(f2.x, f2.y, f3.x, f3.y);
}

__device__ __forceinline__ float edge_score(float4 ta, float4 tb,
                                            float4 xra, float4 xrb,
                                            float4 ata, float4 atb) {
    float p = lrelu(ta.x + xra.x) * ata.x + lrelu(ta.y + xra.y) * ata.y
            + lrelu(ta.z + xra.z) * ata.z + lrelu(ta.w + xra.w) * ata.w
            + lrelu(tb.x + xrb.x) * atb.x + lrelu(tb.y + xrb.y) * atb.y
            + lrelu(tb.z + xrb.z) * atb.z + lrelu(tb.w + xrb.w) * atb.w;
    p += __shfl_xor_sync(0xffffffffu, p, 1);
    p += __shfl_xor_sync(0xffffffffu, p, 2);
    p += __shfl_xor_sync(0xffffffffu, p, 4);
    return p;
}

// one warp per destination node; lane owns halfs [8*lane, 8*lane+8) (one uint4)
__global__ __launch_bounds__(256) void k_attn(const float* __restrict__ att,
                                              const float* __restrict__ gb, int dogelu) {
    int w = (blockIdx.x * blockDim.x + threadIdx.x) >> 5;
    int lane = threadIdx.x & 31;
    if (w >= NN) return;

    float4 xra, xrb;
    h8f(*(const uint4*)(g_xr16 + (size_t)w * HD + lane * 8), xra, xrb);
    const float4* at4 = (const float4*)att;
    float4 ata = at4[2 * lane], atb = at4[2 * lane + 1];

    float4 sa, sb;
    h8f(*(const uint4*)(g_xl16 + (size_t)w * HD + lane * 8), sa, sb);

    int beg = g_rowptr[w], end = g_rowptr[w + 1];
    int j = beg;
    bool have = (j < end);
    int snext = (j + 1 < end) ? g_csrc[j + 1] : 0;
    uint4 nv;
    if (have) {
        int s = g_csrc[j];
        nv = *(const uint4*)(g_xl16 + (size_t)s * HD + lane * 8);
    }

    float denom;
    float acc[8];
    {   // self-loop edge
        float e = edge_score(sa, sb, xra, xrb, ata, atb);
        float ea = __expf(e);
        denom = ea;
        acc[0] = ea * sa.x; acc[1] = ea * sa.y; acc[2] = ea * sa.z; acc[3] = ea * sa.w;
        acc[4] = ea * sb.x; acc[5] = ea * sb.y; acc[6] = ea * sb.z; acc[7] = ea * sb.w;
    }
    while (have) {
        float4 ta, tb;
        h8f(nv, ta, tb);
        j++;
        have = (j < end);
        int s = snext;
        snext = (j + 1 < end) ? g_csrc[j + 1] : 0;
        if (have) nv = *(const uint4*)(g_xl16 + (size_t)s * HD + lane * 8);

        float e = edge_score(ta, tb, xra, xrb, ata, atb);
        float ea = __expf(e);
        denom += ea;
        acc[0] += ea * ta.x; acc[1] += ea * ta.y; acc[2] += ea * ta.z; acc[3] += ea * ta.w;
        acc[4] += ea * tb.x; acc[5] += ea * tb.y; acc[6] += ea * tb.z; acc[7] += ea * tb.w;
    }

    float inv = 1.f / denom;
    float r[8];
#pragma unroll
    for (int c = 0; c < 8; c++) {
        float v = acc[c] * inv;
        v += __shfl_xor_sync(0xffffffffu, v, 8);
        v += __shfl_xor_sync(0xffffffffu, v, 16);
        v *= 0.25f;
        r[c] = v;
    }
    int d0 = 8 * (lane & 7);
#pragma unroll
    for (int c = 0; c < 8; c++) {
        float s = r[c] + gb[d0 + c];
        if (dogelu) s = 0.5f * s * (1.f + erff(s * 0.70710678118654752f));
        r[c] = s;
    }
    if (lane < 8) {
        *(float4*)(g_x + (size_t)w * DIM + d0)     = make_float4(r[0], r[1], r[2], r[3]);
        *(float4*)(g_x + (size_t)w * DIM + d0 + 4) = make_float4(r[4], r[5], r[6], r[7]);
    }
}

// ---------------- pool + head ------------------------------------------------
__global__ void k_pool(const int* __restrict__ batch) {
    int t = blockIdx.x * blockDim.x + threadIdx.x;
    if (t >= NN * DIM) return;
    int n = t >> 6, d = t & 63;
    int gidx = batch[n];
    atomicAdd(&g_pool[gidx * DIM + d], g_x[t]);
    if (d == 0) atomicAdd(&g_cnt[gidx], 1.f);
}
__global__ void k_final(const float* __restrict__ Wc, const float* __restrict__ bc,
                        float* __restrict__ out) {
    int g = blockIdx.x;
    int lane = threadIdx.x;
    float inv = 1.f / fmaxf(g_cnt[g], 1.f);
    float p0 = g_pool[g * DIM + lane] * inv;
    float p1 = g_pool[g * DIM + 32 + lane] * inv;
#pragma unroll
    for (int c = 0; c < NC; c++) {
        float s = p0 * Wc[lane * NC + c] + p1 * Wc[(lane + 32) * NC + c];
#pragma unroll
        for (int o = 16; o; o >>= 1) s += __shfl_xor_sync(0xffffffffu, s, o);
        if (lane == 0) out[g * NC + c] = s + bc[c];
    }
}

// ---------------- launch ------------------------------------------------------
extern "C" void kernel_launch(void* const* d_in, const int* in_sizes, int n_in,
                              void* d_out, int out_size) {
    (void)in_sizes; (void)n_in; (void)out_size;
    const int*   feat  = (const int*)  d_in[0];
    const int*   econ  = (const int*)  d_in[1];
    const int*   batch = (const int*)  d_in[2];
    const float* emb   = (const float*)d_in[3];
    const float* Wl    = (const float*)d_in[4];
    const float* bl    = (const float*)d_in[5];
    const float* Wr    = (const float*)d_in[6];
    const float* br    = (const float*)d_in[7];
    const float* att   = (const float*)d_in[8];
    const float* gbias = (const float*)d_in[9];
    const float* Wc    = (const float*)d_in[10];
    const float* bcv   = (const float*)d_in[11];
    float* out = (float*)d_out;

    const int* src = econ;
    const int* dst = econ + EDG;

    // one-time setup on the first (non-captured) correctness call
    static cudaStream_t s2 = nullptr;
    static cudaEvent_t evFork = nullptr, evJoin = nullptr;
    if (!s2) {
        cudaFuncSetAttribute(k_gemm_mma, cudaFuncAttributeMaxDynamicSharedMemorySize, GSMEM);
        cudaStreamCreateWithFlags(&s2, cudaStreamNonBlocking);
        cudaEventCreateWithFlags(&evFork, cudaEventDisableTiming);
        cudaEventCreateWithFlags(&evJoin, cudaEventDisableTiming);
    }

    // fork: CSR build runs on s2, concurrent with encoder + layer-0 GEMM
    cudaEventRecord(evFork, 0);
    cudaStreamWaitEvent(s2, evFork, 0);
    k_zerodeg<<<(NN + 255) / 256, 256, 0, s2>>>();
    k_hist<<<(EDG + 255) / 256, 256, 0, s2>>>(dst);
    k_scanA<<<NSB, SCAN_B, 0, s2>>>();
    k_scanB<<<1, 64, 0, s2>>>();
    k_scanC<<<(NN + 255) / 256, 256, 0, s2>>>();
    k_scatter<<<(EDG + 255) / 256, 256, 0, s2>>>(src, dst);
    cudaEventRecord(evJoin, s2);

    // main stream: encoder (+wprep) then layer-0 GEMM
    k_encoder<<<(NN * DIM + 255) / 256, 256>>>(feat, emb, Wl, Wr);
    k_gemm_mma<<<(NN + 127) / 128, 256, GSMEM>>>(0, bl, br);

    // join before first attention (needs g_rowptr/g_csrc)
    cudaStreamWaitEvent(0, evJoin, 0);

    for (int l = 0; l < NL; l++) {
        if (l > 0)
            k_gemm_mma<<<(NN + 127) / 128, 256, GSMEM>>>(l, bl + l * HD, br + l * HD);
        k_attn<<<(NN * 32 + 255) / 256, 256>>>(att + l * NH * DIM, gbias + l * DIM,
                                               (l < NL - 1) ? 1 : 0);
    }

    k_pool<<<(NN * DIM + 255) / 256, 256>>>(batch);
    k_final<<<NG, 32>>>(Wc, bcv, out);
}